// round 6
// baseline (speedup 1.0000x reference)
#include <cuda_runtime.h>
#include <math.h>

#define SEQ_T 256
#define NB    64
#define DIM   512
#define TBM   (SEQ_T * NB * DIM)   /* 8388608 */

// ---------------- scratch (static device memory; no runtime alloc) ----------
__device__ float g_iouT[(size_t)SEQ_T * 4 * DIM * NB];  // [t][gate][m][b]
__device__ float g_ctxT[(size_t)SEQ_T * DIM * NB];      // [t][m][b]
__device__ float g_wcsT[(size_t)SEQ_T * DIM * NB];      // [t][m][b]  (tanh applied)
__device__ float g_hT  [(size_t)SEQ_T * DIM * NB];      // [t][m][b]  h history (transposed)
__device__ float g_h0T [DIM * NB];                      // [m][b]
__device__ unsigned g_arrive[128 * 32];                 // per-block epoch, 128B apart
__device__ unsigned g_go;                               // release word

typedef unsigned long long ull;

__device__ __forceinline__ void ffma2(ull& d, ull a, ull b) {
    asm("fma.rn.f32x2 %0, %1, %2, %0;" : "+l"(d) : "l"(a), "l"(b));
}
__device__ __forceinline__ ull packdup(float a) {
    ull r; asm("mov.b64 %0, {%1, %1};" : "=l"(r) : "f"(a)); return r;
}
__device__ __forceinline__ float tanh_fast(float x) {
    float y; asm("tanh.approx.f32 %0, %1;" : "=f"(y) : "f"(x)); return y;
}
__device__ __forceinline__ float sigmoid_fast(float x) {
    return fmaf(0.5f, tanh_fast(0.5f * x), 0.5f);
}
__device__ __forceinline__ unsigned ld_acquire(const unsigned* p) {
    unsigned v;
    asm volatile("ld.acquire.gpu.global.u32 %0, [%1];" : "=r"(v) : "l"(p) : "memory");
    return v;
}
__device__ __forceinline__ void st_release(unsigned* p, unsigned v) {
    asm volatile("st.release.gpu.global.u32 [%0], %1;" :: "l"(p), "r"(v) : "memory");
}

// ---------------------------------------------------------------------------
__global__ void init_kernel(const float* __restrict__ h0) {
    int b = blockIdx.x;          // 64 blocks
    int m = threadIdx.x;         // 512 threads
    g_h0T[m * NB + b] = h0[b * DIM + m];
    int idx = b * 512 + m;
    if (idx < 128 * 32) g_arrive[idx] = 0u;
    if (idx == 0) g_go = 0u;
}

// ---------------------------------------------------------------------------
// Fused fp32 SGEMM (FFMA2): all three projections in one launch.
//   blocks [0,2048)    : iou_x  (N=2048, K=1024 virtual concat)
//   blocks [2048,2560) : ctx    (N=512,  K=512)
//   blocks [2560,3072) : wcs    (N=512,  K=512, tanh epilogue)
// ---------------------------------------------------------------------------
__global__ void __launch_bounds__(256) gemm_fused_kernel(
    const float* __restrict__ inputs, const float* __restrict__ emb_s,
    const float* __restrict__ W_ioux, const float* __restrict__ W_ious,
    const float* __restrict__ b_ioux, const float* __restrict__ b_ious,
    const float* __restrict__ W_fx,   const float* __restrict__ b_fx,
    const float* __restrict__ W_wc,   const float* __restrict__ b_wc)
{
    __shared__ float As[16 * 132];
    __shared__ float Bs[16 * 132];

    const int blk = blockIdx.x;
    int mode, bx, by, K;
    const float *A0, *A1, *B0, *B1, *bias0, *bias1;
    if (blk < 2048) {
        mode = 0; bx = blk & 15; by = blk >> 4; K = 1024;
        A0 = inputs; A1 = emb_s; B0 = W_ioux; B1 = W_ious; bias0 = b_ioux; bias1 = b_ious;
    } else if (blk < 2560) {
        int l = blk - 2048;
        mode = 1; bx = l & 3; by = l >> 2; K = 512;
        A0 = inputs; A1 = nullptr; B0 = W_fx; B1 = nullptr; bias0 = b_fx; bias1 = nullptr;
    } else {
        int l = blk - 2560;
        mode = 2; bx = l & 3; by = l >> 2; K = 512;
        A0 = emb_s; A1 = nullptr; B0 = W_wc; B1 = nullptr; bias0 = b_wc; bias1 = nullptr;
    }

    const int tid = threadIdx.x;
    const int bm  = by * 128;
    const int bn  = bx * 128;
    const int tx  = tid & 15;
    const int ty  = tid >> 4;

    ull accP[8][4];
    #pragma unroll
    for (int i = 0; i < 8; i++)
        #pragma unroll
        for (int j = 0; j < 4; j++) accP[i][j] = 0ull;

    for (int k0 = 0; k0 < K; k0 += 16) {
        const float* Asrc; const float* Bsrc; int ko;
        if (k0 < 512) { Asrc = A0; Bsrc = B0; ko = k0; }
        else          { Asrc = A1; Bsrc = B1; ko = k0 - 512; }

        #pragma unroll
        for (int i = 0; i < 2; i++) {
            int l  = tid + i * 256;
            int r  = l >> 2;
            int c4 = (l & 3) * 4;
            float4 av = *reinterpret_cast<const float4*>(Asrc + (size_t)(bm + r) * 512 + ko + c4);
            As[(c4 + 0) * 132 + r] = av.x;
            As[(c4 + 1) * 132 + r] = av.y;
            As[(c4 + 2) * 132 + r] = av.z;
            As[(c4 + 3) * 132 + r] = av.w;
            float4 bv = *reinterpret_cast<const float4*>(Bsrc + (size_t)(bn + r) * 512 + ko + c4);
            Bs[(c4 + 0) * 132 + r] = bv.x;
            Bs[(c4 + 1) * 132 + r] = bv.y;
            Bs[(c4 + 2) * 132 + r] = bv.z;
            Bs[(c4 + 3) * 132 + r] = bv.w;
        }
        __syncthreads();

        #pragma unroll
        for (int kk = 0; kk < 16; kk++) {
            float a8[8];
            float4 b0 = *reinterpret_cast<const float4*>(&Bs[kk * 132 + tx * 8]);
            float4 b1 = *reinterpret_cast<const float4*>(&Bs[kk * 132 + tx * 8 + 4]);
            *reinterpret_cast<float4*>(a8)     = *reinterpret_cast<const float4*>(&As[kk * 132 + ty * 8]);
            *reinterpret_cast<float4*>(a8 + 4) = *reinterpret_cast<const float4*>(&As[kk * 132 + ty * 8 + 4]);
            ull bp[4];
            bp[0] = reinterpret_cast<const ulonglong2*>(&b0)->x;
            bp[1] = reinterpret_cast<const ulonglong2*>(&b0)->y;
            bp[2] = reinterpret_cast<const ulonglong2*>(&b1)->x;
            bp[3] = reinterpret_cast<const ulonglong2*>(&b1)->y;
            #pragma unroll
            for (int i = 0; i < 8; i++) {
                ull ad = packdup(a8[i]);
                #pragma unroll
                for (int j = 0; j < 4; j++)
                    ffma2(accP[i][j], ad, bp[j]);
            }
        }
        __syncthreads();
    }

    const int col0 = bn + tx * 8;
    float bias[8];
    #pragma unroll
    for (int j = 0; j < 8; j++) {
        float v = bias0[col0 + j];
        if (bias1) v += bias1[col0 + j];
        bias[j] = v;
    }

    #pragma unroll
    for (int i = 0; i < 8; i++) {
        int row = bm + ty * 8 + i;
        int t   = row >> 6;
        int b   = row & 63;
        #pragma unroll
        for (int j = 0; j < 8; j++) {
            float2 pr = *reinterpret_cast<float2*>(&accP[i][j >> 1]);
            float v = ((j & 1) ? pr.y : pr.x) + bias[j];
            int col = col0 + j;
            if (mode == 0) {
                int g  = col >> 9;
                int mc = col & 511;
                g_iouT[(((size_t)t * 4 + g) * 512 + mc) * 64 + b] = v;
            } else if (mode == 1) {
                g_ctxT[(size_t)t * (512 * 64) + (size_t)col * 64 + b] = v;
            } else {
                g_wcsT[(size_t)t * (512 * 64) + (size_t)col * 64 + b] = tanhf(v);
            }
        }
    }
}

// ---------------------------------------------------------------------------
// Persistent weight-stationary scan (FFMA2) + gather/release barrier.
// 128 blocks, 256 threads; weights duplicated (w,w) in ~80KB dynamic smem.
// ---------------------------------------------------------------------------
#define W4TOT 16448                       /* floats: 4 m * (4 kc * 1028) */
#define SCAN_SMEM_FLOATS (W4TOT + 4 * 1032)
#define SCAN_SMEM_BYTES  (SCAN_SMEM_FLOATS * 4)

__global__ void __launch_bounds__(256) scan_kernel(
    const float* __restrict__ W_iouh, const float* __restrict__ b_iouh,
    const float* __restrict__ W_fh,   const float* __restrict__ b_fh,
    const float* __restrict__ c0,     float* __restrict__ out)
{
    extern __shared__ float sm[];

    const int tid   = threadIdx.x;
    const int warp  = tid >> 5;
    const int lane  = tid & 31;
    const int m_l   = warp >> 1;
    const int bhalf = warp & 1;
    const int kc    = (lane >> 3) & 3;
    const int bq    = lane & 7;
    const int m     = blockIdx.x * 4 + m_l;
    const int b_own = bhalf * 32 + bq * 4 + kc;

    // ---- weights into smem, duplicated (w,w) pairs ----
    for (int idx = tid; idx < 8192; idx += 256) {
        int ml = idx >> 11;
        int r  = idx & 2047;
        int c  = r >> 9;
        int r2 = r & 511;
        int i  = r2 >> 2;
        int g  = r2 & 3;
        int mg = blockIdx.x * 4 + ml;
        float w = W_iouh[((size_t)g * 512 + mg) * 512 + c * 128 + i];
        float* p = sm + ml * 4112 + c * 1028 + i * 8 + g * 2;
        p[0] = w; p[1] = w;
    }
    for (int idx = tid; idx < 2048; idx += 256) {
        int ml = idx >> 9;
        int r  = idx & 511;
        int c  = r >> 7;
        int i  = r & 127;
        int mg = blockIdx.x * 4 + ml;
        float w = W_fh[(size_t)mg * 512 + c * 128 + i];
        float* p = sm + W4TOT + ml * 1032 + c * 258 + i * 2;
        p[0] = w; p[1] = w;
    }
    __syncthreads();

    const float bf  = b_iouh[m];
    const float bi  = b_iouh[512 + m];
    const float bo  = b_iouh[1024 + m];
    const float boc = b_iouh[1536 + m];
    const float bfh = b_fh[m];

    float c_reg = c0[(size_t)b_own * 512 + m];
    float hv2 = 0.f;

    const float4* w4f = reinterpret_cast<const float4*>(sm + m_l * 4112 + kc * 1028);
    const float2* w1f = reinterpret_cast<const float2*>(sm + W4TOT + m_l * 1032 + kc * 258);
    const int hoff = kc * 2048 + bhalf * 8 + bq;   // float4 index within step slice

    // prime addends for t = 0
    float af, ai, ao, aoc, act, aw;
    {
        const size_t ib = ((size_t)0 * 4 * 512 + m) * 64 + b_own;
        const size_t sb = (size_t)m * 64 + b_own;
        af  = __ldg(&g_iouT[ib]);
        ai  = __ldg(&g_iouT[ib + 1 * 512 * 64]);
        ao  = __ldg(&g_iouT[ib + 2 * 512 * 64]);
        aoc = __ldg(&g_iouT[ib + 3 * 512 * 64]);
        act = __ldg(&g_ctxT[sb]);
        aw  = __ldg(&g_wcsT[sb]);
    }

    for (int t = 0; t < SEQ_T; t++) {
        const float* hb = (t == 0) ? g_h0T : (g_hT + (size_t)(t - 1) * (DIM * NB));
        const float4* hp = reinterpret_cast<const float4*>(hb) + hoff;

        ull acc2[2][5];
        #pragma unroll
        for (int p = 0; p < 2; p++)
            #pragma unroll
            for (int g = 0; g < 5; g++) acc2[p][g] = 0ull;

        #pragma unroll 8
        for (int i = 0; i < 128; i++) {
            float4 h4 = __ldg(hp + i * 16);
            ulonglong2 hv = *reinterpret_cast<ulonglong2*>(&h4);
            float4 wa = w4f[i * 2];
            float4 wb = w4f[i * 2 + 1];
            float2 wc = w1f[i];
            ull w0 = reinterpret_cast<ulonglong2*>(&wa)->x;
            ull w1 = reinterpret_cast<ulonglong2*>(&wa)->y;
            ull w2 = reinterpret_cast<ulonglong2*>(&wb)->x;
            ull w3 = reinterpret_cast<ulonglong2*>(&wb)->y;
            ull w4 = *reinterpret_cast<ull*>(&wc);
            ffma2(acc2[0][0], hv.x, w0);
            ffma2(acc2[0][1], hv.x, w1);
            ffma2(acc2[0][2], hv.x, w2);
            ffma2(acc2[0][3], hv.x, w3);
            ffma2(acc2[0][4], hv.x, w4);
            ffma2(acc2[1][0], hv.y, w0);
            ffma2(acc2[1][1], hv.y, w1);
            ffma2(acc2[1][2], hv.y, w2);
            ffma2(acc2[1][3], hv.y, w3);
            ffma2(acc2[1][4], hv.y, w4);
        }

        float a[20];
        #pragma unroll
        for (int p = 0; p < 2; p++)
            #pragma unroll
            for (int g = 0; g < 5; g++) {
                float2 v = *reinterpret_cast<float2*>(&acc2[p][g]);
                a[(2 * p + 0) * 5 + g] = v.x;
                a[(2 * p + 1) * 5 + g] = v.y;
            }

        #pragma unroll
        for (int q = 0; q < 20; q++) {
            a[q] += __shfl_xor_sync(0xffffffffu, a[q], 8);
            a[q] += __shfl_xor_sync(0xffffffffu, a[q], 16);
        }

        float fg  = sigmoid_fast(a[kc * 5 + 0] + af  + bf);
        float ig  = sigmoid_fast(a[kc * 5 + 1] + ai  + bi);
        float og  = sigmoid_fast(a[kc * 5 + 2] + ao  + bo);
        float ocg = sigmoid_fast(a[kc * 5 + 3] + aoc + boc);
        float ct  = tanh_fast   (a[kc * 5 + 4] + act + bfh);

        c_reg = ig * ct + fg * c_reg;
        hv2 = og * tanh_fast(c_reg) + ocg * aw;

        const size_t sb = (size_t)t * (512 * 64) + (size_t)m * 64 + b_own;
        g_hT[sb] = hv2;                                               // [t][m][b]
        out[(size_t)t * (NB * DIM) + (size_t)b_own * 512 + m] = hv2;  // [t][b][m]

        // prefetch addends for t+1 (hides L2 latency under the barrier)
        if (t + 1 < SEQ_T) {
            const size_t ib2 = (((size_t)(t + 1) * 4) * 512 + m) * 64 + b_own;
            const size_t sb2 = (size_t)(t + 1) * (512 * 64) + (size_t)m * 64 + b_own;
            af  = __ldg(&g_iouT[ib2]);
            ai  = __ldg(&g_iouT[ib2 + 1 * 512 * 64]);
            ao  = __ldg(&g_iouT[ib2 + 2 * 512 * 64]);
            aoc = __ldg(&g_iouT[ib2 + 3 * 512 * 64]);
            act = __ldg(&g_ctxT[sb2]);
            aw  = __ldg(&g_wcsT[sb2]);
        }

        // ---- gather/release barrier ----
        __syncthreads();                       // all h stores issued block-wide
        if (tid == 0)
            st_release(&g_arrive[blockIdx.x * 32], (unsigned)(t + 1));  // publish

        if (blockIdx.x == 0) {
            if (tid < 128) {
                const unsigned* fp = &g_arrive[tid * 32];
                while (ld_acquire(fp) < (unsigned)(t + 1)) { }
            }
            __syncthreads();                   // all 128 flags acquired
            if (tid == 0) st_release(&g_go, (unsigned)(t + 1));
        } else {
            if (tid == 0) {
                while (ld_acquire(&g_go) < (unsigned)(t + 1)) { }
            }
            __syncthreads();                   // propagate acquire block-wide
        }
    }

    // tails
    out[TBM + (size_t)b_own * 512 + m]            = c_reg;
    out[TBM + NB * DIM + (size_t)b_own * 512 + m] = hv2;
}

// ---------------------------------------------------------------------------
extern "C" void kernel_launch(void* const* d_in, const int* in_sizes, int n_in,
                              void* d_out, int out_size)
{
    const float* inputs = (const float*)d_in[0];
    const float* emb_s  = (const float*)d_in[1];
    const float* c0     = (const float*)d_in[2];
    const float* h0     = (const float*)d_in[3];
    const float* W_ioux = (const float*)d_in[4];
    const float* b_ioux = (const float*)d_in[5];
    const float* W_iouh = (const float*)d_in[6];
    const float* b_iouh = (const float*)d_in[7];
    const float* W_ious = (const float*)d_in[8];
    const float* b_ious = (const float*)d_in[9];
    const float* W_fx   = (const float*)d_in[10];
    const float* b_fx   = (const float*)d_in[11];
    const float* W_fh   = (const float*)d_in[12];
    const float* b_fh   = (const float*)d_in[13];
    const float* W_wc   = (const float*)d_in[14];
    const float* b_wc   = (const float*)d_in[15];
    float* out = (float*)d_out;

    static int smem_set = 0;
    if (!smem_set) {
        cudaFuncSetAttribute(scan_kernel, cudaFuncAttributeMaxDynamicSharedMemorySize,
                             SCAN_SMEM_BYTES);
        smem_set = 1;
    }

    init_kernel<<<64, 512>>>(h0);
    gemm_fused_kernel<<<3072, 256>>>(inputs, emb_s, W_ioux, W_ious, b_ioux, b_ious,
                                     W_fx, b_fx, W_wc, b_wc);
    scan_kernel<<<128, 256, SCAN_SMEM_BYTES>>>(W_iouh, b_iouh, W_fh, b_fh, c0, out);
}

// round 7
// speedup vs baseline: 1.4907x; 1.4907x over previous
#include <cuda_runtime.h>
#include <math.h>

#define SEQ_T 256
#define NB    64
#define DIM   512
#define TBM   (SEQ_T * NB * DIM)   /* 8388608 */

// ---------------- scratch (static device memory; no runtime alloc) ----------
__device__ float g_iouT[(size_t)SEQ_T * 4 * DIM * NB];  // [t][gate][m][b]
__device__ float g_ctxT[(size_t)SEQ_T * DIM * NB];      // [t][m][b]
__device__ float g_wcsT[(size_t)SEQ_T * DIM * NB];      // [t][m][b]  (tanh applied)
__device__ float g_hT  [(size_t)SEQ_T * DIM * NB];      // [t][m][b]  h history
__device__ float g_h0T [DIM * NB];                      // [m][b]
__device__ unsigned g_cnt;                              // grid-barrier counter

typedef unsigned long long ull;

__device__ __forceinline__ void ffma2(ull& d, ull a, ull b) {
    asm("fma.rn.f32x2 %0, %1, %2, %0;" : "+l"(d) : "l"(a), "l"(b));
}
__device__ __forceinline__ ull packdup(float a) {
    ull r; asm("mov.b64 %0, {%1, %1};" : "=l"(r) : "f"(a)); return r;
}
__device__ __forceinline__ float tanh_fast(float x) {
    float y; asm("tanh.approx.f32 %0, %1;" : "=f"(y) : "f"(x)); return y;
}
__device__ __forceinline__ float sigmoid_fast(float x) {
    return fmaf(0.5f, tanh_fast(0.5f * x), 0.5f);
}

// ---------------------------------------------------------------------------
__global__ void init_kernel(const float* __restrict__ h0) {
    int b = blockIdx.x;          // 64 blocks
    int m = threadIdx.x;         // 512 threads
    g_h0T[m * NB + b] = h0[b * DIM + m];
    if (b == 0 && m == 0) g_cnt = 0u;
}

// ---------------------------------------------------------------------------
// Fused fp32 SGEMM (FFMA2): all three projections in one launch.
// ---------------------------------------------------------------------------
__global__ void __launch_bounds__(256) gemm_fused_kernel(
    const float* __restrict__ inputs, const float* __restrict__ emb_s,
    const float* __restrict__ W_ioux, const float* __restrict__ W_ious,
    const float* __restrict__ b_ioux, const float* __restrict__ b_ious,
    const float* __restrict__ W_fx,   const float* __restrict__ b_fx,
    const float* __restrict__ W_wc,   const float* __restrict__ b_wc)
{
    __shared__ float As[16 * 132];
    __shared__ float Bs[16 * 132];

    const int blk = blockIdx.x;
    int mode, bx, by, K;
    const float *A0, *A1, *B0, *B1, *bias0, *bias1;
    if (blk < 2048) {
        mode = 0; bx = blk & 15; by = blk >> 4; K = 1024;
        A0 = inputs; A1 = emb_s; B0 = W_ioux; B1 = W_ious; bias0 = b_ioux; bias1 = b_ious;
    } else if (blk < 2560) {
        int l = blk - 2048;
        mode = 1; bx = l & 3; by = l >> 2; K = 512;
        A0 = inputs; A1 = nullptr; B0 = W_fx; B1 = nullptr; bias0 = b_fx; bias1 = nullptr;
    } else {
        int l = blk - 2560;
        mode = 2; bx = l & 3; by = l >> 2; K = 512;
        A0 = emb_s; A1 = nullptr; B0 = W_wc; B1 = nullptr; bias0 = b_wc; bias1 = nullptr;
    }

    const int tid = threadIdx.x;
    const int bm  = by * 128;
    const int bn  = bx * 128;
    const int tx  = tid & 15;
    const int ty  = tid >> 4;

    ull accP[8][4];
    #pragma unroll
    for (int i = 0; i < 8; i++)
        #pragma unroll
        for (int j = 0; j < 4; j++) accP[i][j] = 0ull;

    for (int k0 = 0; k0 < K; k0 += 16) {
        const float* Asrc; const float* Bsrc; int ko;
        if (k0 < 512) { Asrc = A0; Bsrc = B0; ko = k0; }
        else          { Asrc = A1; Bsrc = B1; ko = k0 - 512; }

        #pragma unroll
        for (int i = 0; i < 2; i++) {
            int l  = tid + i * 256;
            int r  = l >> 2;
            int c4 = (l & 3) * 4;
            float4 av = *reinterpret_cast<const float4*>(Asrc + (size_t)(bm + r) * 512 + ko + c4);
            As[(c4 + 0) * 132 + r] = av.x;
            As[(c4 + 1) * 132 + r] = av.y;
            As[(c4 + 2) * 132 + r] = av.z;
            As[(c4 + 3) * 132 + r] = av.w;
            float4 bv = *reinterpret_cast<const float4*>(Bsrc + (size_t)(bn + r) * 512 + ko + c4);
            Bs[(c4 + 0) * 132 + r] = bv.x;
            Bs[(c4 + 1) * 132 + r] = bv.y;
            Bs[(c4 + 2) * 132 + r] = bv.z;
            Bs[(c4 + 3) * 132 + r] = bv.w;
        }
        __syncthreads();

        #pragma unroll
        for (int kk = 0; kk < 16; kk++) {
            float a8[8];
            float4 b0 = *reinterpret_cast<const float4*>(&Bs[kk * 132 + tx * 8]);
            float4 b1 = *reinterpret_cast<const float4*>(&Bs[kk * 132 + tx * 8 + 4]);
            *reinterpret_cast<float4*>(a8)     = *reinterpret_cast<const float4*>(&As[kk * 132 + ty * 8]);
            *reinterpret_cast<float4*>(a8 + 4) = *reinterpret_cast<const float4*>(&As[kk * 132 + ty * 8 + 4]);
            ull bp[4];
            bp[0] = reinterpret_cast<const ulonglong2*>(&b0)->x;
            bp[1] = reinterpret_cast<const ulonglong2*>(&b0)->y;
            bp[2] = reinterpret_cast<const ulonglong2*>(&b1)->x;
            bp[3] = reinterpret_cast<const ulonglong2*>(&b1)->y;
            #pragma unroll
            for (int i = 0; i < 8; i++) {
                ull ad = packdup(a8[i]);
                #pragma unroll
                for (int j = 0; j < 4; j++)
                    ffma2(accP[i][j], ad, bp[j]);
            }
        }
        __syncthreads();
    }

    const int col0 = bn + tx * 8;
    float bias[8];
    #pragma unroll
    for (int j = 0; j < 8; j++) {
        float v = bias0[col0 + j];
        if (bias1) v += bias1[col0 + j];
        bias[j] = v;
    }

    #pragma unroll
    for (int i = 0; i < 8; i++) {
        int row = bm + ty * 8 + i;
        int t   = row >> 6;
        int b   = row & 63;
        #pragma unroll
        for (int j = 0; j < 8; j++) {
            float2 pr = *reinterpret_cast<float2*>(&accP[i][j >> 1]);
            float v = ((j & 1) ? pr.y : pr.x) + bias[j];
            int col = col0 + j;
            if (mode == 0) {
                int g  = col >> 9;
                int mc = col & 511;
                g_iouT[(((size_t)t * 4 + g) * 512 + mc) * 64 + b] = v;
            } else if (mode == 1) {
                g_ctxT[(size_t)t * (512 * 64) + (size_t)col * 64 + b] = v;
            } else {
                g_wcsT[(size_t)t * (512 * 64) + (size_t)col * 64 + b] = tanhf(v);
            }
        }
    }
}

// ---------------------------------------------------------------------------
// Persistent scan, L1TEX-lean layout.
// 128 blocks, 256 threads. warp = mp(2)*4 + iq(4); lane = kc(4)*8 + bq(8).
// Thread: 2 m (mpair), 8 b (two float4), k = kc*128 + iq*32 + i (i<32).
// Weights un-duplicated in smem (broadcast LDS), dup'd in regs via mov.b64.
// kc-reduce via shfl; iq-reduce via smem buf; 128 owner threads (m, b-pair)
// hold c in registers and do gates + stores. R5 atomic barrier.
// ---------------------------------------------------------------------------
#define SM4_BYTES 32768                 /* 4m * 512k * float4 */
#define SM1_BYTES 8192                  /* 2mp * 512k * float2 */
#define BUF_BYTES 20480                 /* 8 warps * 40 combos * 8 bq * ull */
#define SCAN_SMEM_BYTES (SM4_BYTES + SM1_BYTES + BUF_BYTES)

__global__ void __launch_bounds__(256) scan_kernel(
    const float* __restrict__ W_iouh, const float* __restrict__ b_iouh,
    const float* __restrict__ W_fh,   const float* __restrict__ b_fh,
    const float* __restrict__ c0,     float* __restrict__ out)
{
    extern __shared__ char smraw[];
    float4* sm4w = reinterpret_cast<float4*>(smraw);
    float2* sm1w = reinterpret_cast<float2*>(smraw + SM4_BYTES);
    ull*    buf  = reinterpret_cast<ull*>(smraw + SM4_BYTES + SM1_BYTES);

    const int tid  = threadIdx.x;
    const int warp = tid >> 5;
    const int lane = tid & 31;
    const int mp   = warp >> 2;     // m-pair (0,1)
    const int iq   = warp & 3;      // k-quarter within kc slice
    const int kc   = lane >> 3;
    const int bq   = lane & 7;
    const int blk  = blockIdx.x;

    // ---- weights into smem (un-duplicated) ----
    for (int idx = tid; idx < 2048; idx += 256) {
        int ml = idx >> 9;
        int k  = idx & 511;
        int mg = blk * 4 + ml;
        sm4w[ml * 512 + k] = make_float4(
            W_iouh[(size_t)mg * 512 + k],
            W_iouh[(size_t)(512 + mg) * 512 + k],
            W_iouh[(size_t)(1024 + mg) * 512 + k],
            W_iouh[(size_t)(1536 + mg) * 512 + k]);
    }
    for (int idx = tid; idx < 1024; idx += 256) {
        int mpp = idx >> 9;
        int k   = idx & 511;
        int mg0 = blk * 4 + 2 * mpp;
        sm1w[mpp * 512 + k] = make_float2(W_fh[(size_t)mg0 * 512 + k],
                                          W_fh[(size_t)(mg0 + 1) * 512 + k]);
    }
    __syncthreads();

    // ---- owner setup (tid < 128): owns (m_own, b0..b0+1) ----
    const int m_own = tid >> 5;            // 0..3 (valid when tid<128)
    const int b0    = 2 * (tid & 31);
    const int m_g   = blk * 4 + m_own;
    const int mp_o  = m_own >> 1;
    const int ml_o  = m_own & 1;
    int bq_o, pr_o;
    if (b0 < 32) { bq_o = b0 >> 2; pr_o = (b0 >> 1) & 1; }
    else         { int bb = b0 - 32; bq_o = bb >> 2; pr_o = 2 + ((bb >> 1) & 1); }

    float bfv = 0.f, biv = 0.f, bov = 0.f, bocv = 0.f, bfhv = 0.f;
    float2 c_reg = make_float2(0.f, 0.f);
    float2 af2, ai2, ao2, aoc2, act2, aw2;
    if (tid < 128) {
        bfv  = b_iouh[m_g];
        biv  = b_iouh[512 + m_g];
        bov  = b_iouh[1024 + m_g];
        bocv = b_iouh[1536 + m_g];
        bfhv = b_fh[m_g];
        c_reg.x = c0[(size_t)b0 * 512 + m_g];
        c_reg.y = c0[(size_t)(b0 + 1) * 512 + m_g];
        // addends for t = 0
        const size_t ib = ((size_t)0 * 4 * 512 + m_g) * 64 + b0;
        const size_t sb = (size_t)m_g * 64 + b0;
        af2  = *reinterpret_cast<const float2*>(&g_iouT[ib]);
        ai2  = *reinterpret_cast<const float2*>(&g_iouT[ib + 1 * 512 * 64]);
        ao2  = *reinterpret_cast<const float2*>(&g_iouT[ib + 2 * 512 * 64]);
        aoc2 = *reinterpret_cast<const float2*>(&g_iouT[ib + 3 * 512 * 64]);
        act2 = *reinterpret_cast<const float2*>(&g_ctxT[sb]);
        aw2  = *reinterpret_cast<const float2*>(&g_wcsT[sb]);
    }

    const int kbase = kc * 128 + iq * 32;
    const int fbase = kbase * 16 + bq;
    float2 h_keep = make_float2(0.f, 0.f);

    for (int t = 0; t < SEQ_T; t++) {
        const float* hb = (t == 0) ? g_h0T : (g_hT + (size_t)(t - 1) * (DIM * NB));
        const float4* hp = reinterpret_cast<const float4*>(hb);

        ull A[2][5][4];
        #pragma unroll
        for (int a1 = 0; a1 < 2; a1++)
            #pragma unroll
            for (int a2 = 0; a2 < 5; a2++)
                #pragma unroll
                for (int a3 = 0; a3 < 4; a3++) A[a1][a2][a3] = 0ull;

        #pragma unroll 4
        for (int i = 0; i < 32; i++) {
            float4 hl = __ldg(hp + fbase + i * 16);
            float4 hh = __ldg(hp + fbase + 8 + i * 16);
            ull hpair[4];
            hpair[0] = reinterpret_cast<ulonglong2*>(&hl)->x;
            hpair[1] = reinterpret_cast<ulonglong2*>(&hl)->y;
            hpair[2] = reinterpret_cast<ulonglong2*>(&hh)->x;
            hpair[3] = reinterpret_cast<ulonglong2*>(&hh)->y;

            float wa[10];
            *reinterpret_cast<float4*>(wa + 0) = sm4w[(mp * 2 + 0) * 512 + kbase + i];
            *reinterpret_cast<float4*>(wa + 4) = sm4w[(mp * 2 + 1) * 512 + kbase + i];
            *reinterpret_cast<float2*>(wa + 8) = sm1w[mp * 512 + kbase + i];

            #pragma unroll
            for (int ml = 0; ml < 2; ml++) {
                #pragma unroll
                for (int g = 0; g < 5; g++) {
                    float w = (g < 4) ? wa[ml * 4 + g] : wa[8 + ml];
                    ull wd = packdup(w);
                    #pragma unroll
                    for (int pr = 0; pr < 4; pr++)
                        ffma2(A[ml][g][pr], hpair[pr], wd);
                }
            }
        }

        // ---- kc reduction (shfl over lane bits 3,4) ----
        ull* Af = &A[0][0][0];
        #pragma unroll
        for (int c = 0; c < 40; c++) {
            float2 v = *reinterpret_cast<float2*>(&Af[c]);
            v.x += __shfl_xor_sync(0xffffffffu, v.x, 8);
            v.y += __shfl_xor_sync(0xffffffffu, v.y, 8);
            v.x += __shfl_xor_sync(0xffffffffu, v.x, 16);
            v.y += __shfl_xor_sync(0xffffffffu, v.y, 16);
            Af[c] = *reinterpret_cast<ull*>(&v);
        }

        // ---- iq reduction staging: lane kc stores its 10 combos ----
        #pragma unroll
        for (int cc = 0; cc < 10; cc++) {
            int c = kc * 10 + cc;
            buf[((size_t)warp * 40 + c) * 8 + bq] = Af[c];
        }
        __syncthreads();

        // ---- owners: finish reduction + gates ----
        if (tid < 128) {
            float2 s[5];
            #pragma unroll
            for (int g = 0; g < 5; g++) {
                int c = ml_o * 20 + g * 4 + pr_o;
                float2 acc = make_float2(0.f, 0.f);
                #pragma unroll
                for (int q = 0; q < 4; q++) {
                    ull v = buf[((size_t)(mp_o * 4 + q) * 40 + c) * 8 + bq_o];
                    float2 f = *reinterpret_cast<float2*>(&v);
                    acc.x += f.x; acc.y += f.y;
                }
                s[g] = acc;
            }

            float fgx  = sigmoid_fast(s[0].x + af2.x + bfv);
            float fgy  = sigmoid_fast(s[0].y + af2.y + bfv);
            float igx  = sigmoid_fast(s[1].x + ai2.x + biv);
            float igy  = sigmoid_fast(s[1].y + ai2.y + biv);
            float ogx  = sigmoid_fast(s[2].x + ao2.x + bov);
            float ogy  = sigmoid_fast(s[2].y + ao2.y + bov);
            float ocgx = sigmoid_fast(s[3].x + aoc2.x + bocv);
            float ocgy = sigmoid_fast(s[3].y + aoc2.y + bocv);
            float ctx_ = tanh_fast(s[4].x + act2.x + bfhv);
            float cty_ = tanh_fast(s[4].y + act2.y + bfhv);

            c_reg.x = igx * ctx_ + fgx * c_reg.x;
            c_reg.y = igy * cty_ + fgy * c_reg.y;
            h_keep.x = ogx * tanh_fast(c_reg.x) + ocgx * aw2.x;
            h_keep.y = ogy * tanh_fast(c_reg.y) + ocgy * aw2.y;

            *reinterpret_cast<float2*>(&g_hT[(size_t)t * (DIM * NB) + (size_t)m_g * 64 + b0]) = h_keep;
            out[(size_t)t * (NB * DIM) + (size_t)b0 * 512 + m_g]       = h_keep.x;
            out[(size_t)t * (NB * DIM) + (size_t)(b0 + 1) * 512 + m_g] = h_keep.y;

            // prefetch addends for t+1
            if (t + 1 < SEQ_T) {
                const size_t ib2 = (((size_t)(t + 1) * 4) * 512 + m_g) * 64 + b0;
                const size_t sb2 = (size_t)(t + 1) * (512 * 64) + (size_t)m_g * 64 + b0;
                af2  = *reinterpret_cast<const float2*>(&g_iouT[ib2]);
                ai2  = *reinterpret_cast<const float2*>(&g_iouT[ib2 + 1 * 512 * 64]);
                ao2  = *reinterpret_cast<const float2*>(&g_iouT[ib2 + 2 * 512 * 64]);
                aoc2 = *reinterpret_cast<const float2*>(&g_iouT[ib2 + 3 * 512 * 64]);
                act2 = *reinterpret_cast<const float2*>(&g_ctxT[sb2]);
                aw2  = *reinterpret_cast<const float2*>(&g_wcsT[sb2]);
            }
        }

        // ---- grid barrier (R5, measured-best): fence + atomic + spin ----
        __syncthreads();
        if (tid == 0) {
            __threadfence();
            atomicAdd(&g_cnt, 1u);
            const unsigned target = (unsigned)gridDim.x * (unsigned)(t + 1);
            while (*reinterpret_cast<volatile unsigned*>(&g_cnt) < target) { }
            __threadfence();
        }
        __syncthreads();
    }

    // tails
    if (tid < 128) {
        out[TBM + (size_t)b0 * 512 + m_g]                 = c_reg.x;
        out[TBM + (size_t)(b0 + 1) * 512 + m_g]           = c_reg.y;
        out[TBM + NB * DIM + (size_t)b0 * 512 + m_g]       = h_keep.x;
        out[TBM + NB * DIM + (size_t)(b0 + 1) * 512 + m_g] = h_keep.y;
    }
}

// ---------------------------------------------------------------------------
extern "C" void kernel_launch(void* const* d_in, const int* in_sizes, int n_in,
                              void* d_out, int out_size)
{
    const float* inputs = (const float*)d_in[0];
    const float* emb_s  = (const float*)d_in[1];
    const float* c0     = (const float*)d_in[2];
    const float* h0     = (const float*)d_in[3];
    const float* W_ioux = (const float*)d_in[4];
    const float* b_ioux = (const float*)d_in[5];
    const float* W_iouh = (const float*)d_in[6];
    const float* b_iouh = (const float*)d_in[7];
    const float* W_ious = (const float*)d_in[8];
    const float* b_ious = (const float*)d_in[9];
    const float* W_fx   = (const float*)d_in[10];
    const float* b_fx   = (const float*)d_in[11];
    const float* W_fh   = (const float*)d_in[12];
    const float* b_fh   = (const float*)d_in[13];
    const float* W_wc   = (const float*)d_in[14];
    const float* b_wc   = (const float*)d_in[15];
    float* out = (float*)d_out;

    static int smem_set = 0;
    if (!smem_set) {
        cudaFuncSetAttribute(scan_kernel, cudaFuncAttributeMaxDynamicSharedMemorySize,
                             SCAN_SMEM_BYTES);
        smem_set = 1;
    }

    init_kernel<<<64, 512>>>(h0);
    gemm_fused_kernel<<<3072, 256>>>(inputs, emb_s, W_ioux, W_ious, b_ioux, b_ious,
                                     W_fx, b_fx, W_wc, b_wc);
    scan_kernel<<<128, 256, SCAN_SMEM_BYTES>>>(W_iouh, b_iouh, W_fh, b_fh, c0, out);
}

// round 9
// speedup vs baseline: 1.7510x; 1.1746x over previous
#include <cuda_runtime.h>
#include <cuda_bf16.h>
#include <math.h>
#include <stdint.h>

#define SEQ_T 256
#define NB    64
#define DIM   512
#define TBM   (SEQ_T * NB * DIM)   /* 8388608 */

// ---------------- scratch (static device memory; no runtime alloc) ----------
__device__ float g_iouT[(size_t)SEQ_T * 4 * DIM * NB];  // [t][gate][m][b]
__device__ float g_ctxT[(size_t)SEQ_T * DIM * NB];      // [t][m][b]
__device__ float g_wcsT[(size_t)SEQ_T * DIM * NB];      // [t][m][b]  (tanh applied)
__device__ float g_hT  [(size_t)SEQ_T * DIM * NB];      // [t][m][b]  h history
__device__ float g_h0T [DIM * NB];                      // [m][b]
__device__ unsigned g_cnt;                              // grid-barrier counter

typedef unsigned long long ull;

__device__ __forceinline__ void ffma2(ull& d, ull a, ull b) {
    asm("fma.rn.f32x2 %0, %1, %2, %0;" : "+l"(d) : "l"(a), "l"(b));
}
__device__ __forceinline__ ull packdup(float a) {
    ull r; asm("mov.b64 %0, {%1, %1};" : "=l"(r) : "f"(a)); return r;
}
__device__ __forceinline__ float tanh_fast(float x) {
    float y; asm("tanh.approx.f32 %0, %1;" : "=f"(y) : "f"(x)); return y;
}
__device__ __forceinline__ float sigmoid_fast(float x) {
    return fmaf(0.5f, tanh_fast(0.5f * x), 0.5f);
}
__device__ __forceinline__ uint32_t smem_u32(const void* p) {
    uint32_t a;
    asm("{ .reg .u64 t; cvta.to.shared.u64 t, %1; cvt.u32.u64 %0, t; }" : "=r"(a) : "l"(p));
    return a;
}
__device__ __forceinline__ void ldsm4(uint32_t* r, uint32_t addr) {
    asm volatile("ldmatrix.sync.aligned.m8n8.x4.shared.b16 {%0,%1,%2,%3}, [%4];"
                 : "=r"(r[0]), "=r"(r[1]), "=r"(r[2]), "=r"(r[3]) : "r"(addr));
}
__device__ __forceinline__ void mma_bf16(float* d, const uint32_t* a, const uint32_t* b) {
    asm volatile(
        "mma.sync.aligned.m16n8k16.row.col.f32.bf16.bf16.f32 "
        "{%0,%1,%2,%3}, {%4,%5,%6,%7}, {%8,%9}, {%0,%1,%2,%3};"
        : "+f"(d[0]), "+f"(d[1]), "+f"(d[2]), "+f"(d[3])
        : "r"(a[0]), "r"(a[1]), "r"(a[2]), "r"(a[3]), "r"(b[0]), "r"(b[1]));
}

// ---------------------------------------------------------------------------
__global__ void init_kernel(const float* __restrict__ h0) {
    int b = blockIdx.x;          // 64 blocks
    int m = threadIdx.x;         // 512 threads
    g_h0T[m * NB + b] = h0[b * DIM + m];
    if (b == 0 && m == 0) g_cnt = 0u;
}

// ---------------------------------------------------------------------------
// HMMA fused GEMM (mma.sync m16n8k16 bf16, split-precision hi+lo, fp32 accum).
//   blocks [0,2048)    : iou_x  (N=2048, K=1024 virtual concat), 128x128 tiles
//   blocks [2048,2560) : ctx    (N=512,  K=512)
//   blocks [2560,3072) : wcs    (N=512,  K=512, tanh epilogue)
// K staged in 32-col chunks; A/B converted fp32 -> bf16 hi+lo into padded smem
// (row stride 40 bf16 = 80B, conflict-free for ldmatrix). 3 mma passes per
// fragment pair (hh, hl, lh). 512 threads, 16 warps, warp tile 32x32.
// ---------------------------------------------------------------------------
#define GB_BUF   40960                /* one buffer: 4 tiles * 128*40*2B */
#define GB_A_HI  0
#define GB_A_LO  10240
#define GB_B_HI  20480
#define GB_B_LO  30720
#define G_SMEM_TOTAL (2 * GB_BUF)     /* 81920; epilogue (128*136*4=69632) reuses it */

__device__ __forceinline__ void store_hilo(char* hi, char* lo, int byteoff, float4 v) {
    __nv_bfloat16 hx = __float2bfloat16_rn(v.x);
    __nv_bfloat16 hy = __float2bfloat16_rn(v.y);
    __nv_bfloat16 hz = __float2bfloat16_rn(v.z);
    __nv_bfloat16 hw = __float2bfloat16_rn(v.w);
    __nv_bfloat16 lx = __float2bfloat16_rn(v.x - __bfloat162float(hx));
    __nv_bfloat16 ly = __float2bfloat16_rn(v.y - __bfloat162float(hy));
    __nv_bfloat16 lz = __float2bfloat16_rn(v.z - __bfloat162float(hz));
    __nv_bfloat16 lw = __float2bfloat16_rn(v.w - __bfloat162float(hw));
    uint2 hp, lp;
    hp.x = ((unsigned)__bfloat16_as_ushort(hy) << 16) | __bfloat16_as_ushort(hx);
    hp.y = ((unsigned)__bfloat16_as_ushort(hw) << 16) | __bfloat16_as_ushort(hz);
    lp.x = ((unsigned)__bfloat16_as_ushort(ly) << 16) | __bfloat16_as_ushort(lx);
    lp.y = ((unsigned)__bfloat16_as_ushort(lw) << 16) | __bfloat16_as_ushort(lz);
    *reinterpret_cast<uint2*>(hi + byteoff) = hp;
    *reinterpret_cast<uint2*>(lo + byteoff) = lp;
}

__global__ void __launch_bounds__(512) gemm_tc_kernel(
    const float* __restrict__ inputs, const float* __restrict__ emb_s,
    const float* __restrict__ W_ioux, const float* __restrict__ W_ious,
    const float* __restrict__ b_ioux, const float* __restrict__ b_ious,
    const float* __restrict__ W_fx,   const float* __restrict__ b_fx,
    const float* __restrict__ W_wc,   const float* __restrict__ b_wc)
{
    extern __shared__ char smem[];
    __shared__ float bias_sm[128];
    const uint32_t sbase = smem_u32(smem);

    const int tid  = threadIdx.x;
    const int wid  = tid >> 5;
    const int lane = tid & 31;
    const int blk  = blockIdx.x;

    int mode, bx, by, K;
    const float *A0, *A1, *B0, *B1, *bias0, *bias1;
    if (blk < 2048) {
        mode = 0; bx = blk & 15; by = blk >> 4; K = 1024;
        A0 = inputs; A1 = emb_s; B0 = W_ioux; B1 = W_ious; bias0 = b_ioux; bias1 = b_ious;
    } else if (blk < 2560) {
        int l = blk - 2048;
        mode = 1; bx = l & 3; by = l >> 2; K = 512;
        A0 = inputs; A1 = nullptr; B0 = W_fx; B1 = nullptr; bias0 = b_fx; bias1 = nullptr;
    } else {
        int l = blk - 2560;
        mode = 2; bx = l & 3; by = l >> 2; K = 512;
        A0 = emb_s; A1 = nullptr; B0 = W_wc; B1 = nullptr; bias0 = b_wc; bias1 = nullptr;
    }
    const int bm = by * 128;
    const int bn = bx * 128;
    const int t0 = bm >> 6;

    if (tid < 128) {
        float v = bias0[bn + tid];
        if (bias1) v += bias1[bn + tid];
        bias_sm[tid] = v;
    }

    const int m0 = (wid & 3) * 32;
    const int n0 = (wid >> 2) * 32;

    float acc[2][4][4];
    #pragma unroll
    for (int i = 0; i < 2; i++)
        #pragma unroll
        for (int j = 0; j < 4; j++)
            #pragma unroll
            for (int e = 0; e < 4; e++) acc[i][j][e] = 0.f;

    // lane-dependent ldmatrix byte offsets (row stride 80B)
    const uint32_t aoff = (uint32_t)((lane & 15) * 80 + (lane >> 4) * 16);
    const uint32_t boff = (uint32_t)((((lane >> 4) << 3) + (lane & 7)) * 80 + ((lane >> 3) & 1) * 16);

    const int nc = K >> 5;
    for (int c = 0; c < nc; c++) {
        const int p = c & 1;
        char* bufp = smem + p * GB_BUF;
        const uint32_t bufb = sbase + p * GB_BUF;
        const int ko = (c & 15) * 32;
        const float* Ap = (c < 16) ? A0 : A1;
        const float* Bp = (c < 16) ? B0 : B1;

        // ---- stage chunk: 128 rows x 32 cols fp32 -> bf16 hi/lo (A and B) ----
        #pragma unroll
        for (int i = 0; i < 2; i++) {
            int idx = tid + i * 512;       // 0..1023
            int r   = idx >> 3;
            int j4  = idx & 7;
            int bo  = r * 80 + j4 * 8;
            float4 va = __ldg(reinterpret_cast<const float4*>(
                              Ap + (size_t)(bm + r) * 512 + ko) + j4);
            store_hilo(bufp + GB_A_HI, bufp + GB_A_LO, bo, va);
            float4 vb = __ldg(reinterpret_cast<const float4*>(
                              Bp + (size_t)(bn + r) * 512 + ko) + j4);
            store_hilo(bufp + GB_B_HI, bufp + GB_B_LO, bo, vb);
        }
        __syncthreads();

        // ---- mma over this chunk: 2 k16 steps ----
        #pragma unroll
        for (int s = 0; s < 2; s++) {
            const uint32_t kkb = s * 32;   // 16 bf16 cols = 32 bytes
            uint32_t a_h[2][4], a_l[2][4], b_h[2][4], b_l[2][4];
            #pragma unroll
            for (int mt = 0; mt < 2; mt++) {
                uint32_t ad = bufb + (uint32_t)((m0 + mt * 16) * 80) + aoff + kkb;
                ldsm4(a_h[mt], ad + GB_A_HI);
                ldsm4(a_l[mt], ad + GB_A_LO);
            }
            #pragma unroll
            for (int pq = 0; pq < 2; pq++) {
                uint32_t bd = bufb + (uint32_t)((n0 + pq * 16) * 80) + boff + kkb;
                ldsm4(b_h[pq], bd + GB_B_HI);
                ldsm4(b_l[pq], bd + GB_B_LO);
            }
            #pragma unroll
            for (int mt = 0; mt < 2; mt++) {
                #pragma unroll
                for (int nt = 0; nt < 4; nt++) {
                    const uint32_t* bh = &b_h[nt >> 1][(nt & 1) * 2];
                    const uint32_t* bl = &b_l[nt >> 1][(nt & 1) * 2];
                    mma_bf16(acc[mt][nt], a_h[mt], bh);
                    mma_bf16(acc[mt][nt], a_h[mt], bl);
                    mma_bf16(acc[mt][nt], a_l[mt], bh);
                }
            }
        }
        __syncthreads();
    }

    // ---- epilogue: acc -> smem transpose (stride 136) -> coalesced stores ----
    float* ep = reinterpret_cast<float*>(smem);
    #pragma unroll
    for (int mt = 0; mt < 2; mt++)
        #pragma unroll
        for (int nt = 0; nt < 4; nt++)
            #pragma unroll
            for (int e = 0; e < 4; e++) {
                int m = m0 + mt * 16 + (lane >> 2) + (e >> 1) * 8;
                int n = n0 + nt * 8 + (lane & 3) * 2 + (e & 1);
                float v = acc[mt][nt][e] + bias_sm[n];
                if (mode == 2) v = tanhf(v);
                ep[n * 136 + m] = v;
            }
    __syncthreads();

    #pragma unroll
    for (int i = 0; i < 8; i++) {
        int q   = tid + i * 512;          // 0..4095
        int col = q >> 5;
        int f4  = q & 31;
        int m   = f4 * 4;
        float4 val = *reinterpret_cast<float4*>(ep + col * 136 + m);
        int cn = bn + col;
        int t  = t0 + (m >> 6);
        int b  = m & 63;
        float* dst;
        if (mode == 0)
            dst = g_iouT + (((size_t)t * 4 + (cn >> 9)) * 512 + (cn & 511)) * 64 + b;
        else if (mode == 1)
            dst = g_ctxT + ((size_t)t * 512 + cn) * 64 + b;
        else
            dst = g_wcsT + ((size_t)t * 512 + cn) * 64 + b;
        *reinterpret_cast<float4*>(dst) = val;
    }
}

// ---------------------------------------------------------------------------
// Persistent scan (unchanged from R7): L1TEX-lean layout, FFMA2, atomic barrier.
// ---------------------------------------------------------------------------
#define SM4_BYTES 32768
#define SM1_BYTES 8192
#define BUF_BYTES 20480
#define SCAN_SMEM_BYTES (SM4_BYTES + SM1_BYTES + BUF_BYTES)

__global__ void __launch_bounds__(256) scan_kernel(
    const float* __restrict__ W_iouh, const float* __restrict__ b_iouh,
    const float* __restrict__ W_fh,   const float* __restrict__ b_fh,
    const float* __restrict__ c0,     float* __restrict__ out)
{
    extern __shared__ char smraw[];
    float4* sm4w = reinterpret_cast<float4*>(smraw);
    float2* sm1w = reinterpret_cast<float2*>(smraw + SM4_BYTES);
    ull*    buf  = reinterpret_cast<ull*>(smraw + SM4_BYTES + SM1_BYTES);

    const int tid  = threadIdx.x;
    const int warp = tid >> 5;
    const int lane = tid & 31;
    const int mp   = warp >> 2;
    const int iq   = warp & 3;
    const int kc   = lane >> 3;
    const int bq   = lane & 7;
    const int blk  = blockIdx.x;

    for (int idx = tid; idx < 2048; idx += 256) {
        int ml = idx >> 9;
        int k  = idx & 511;
        int mg = blk * 4 + ml;
        sm4w[ml * 512 + k] = make_float4(
            W_iouh[(size_t)mg * 512 + k],
            W_iouh[(size_t)(512 + mg) * 512 + k],
            W_iouh[(size_t)(1024 + mg) * 512 + k],
            W_iouh[(size_t)(1536 + mg) * 512 + k]);
    }
    for (int idx = tid; idx < 1024; idx += 256) {
        int mpp = idx >> 9;
        int k   = idx & 511;
        int mg0 = blk * 4 + 2 * mpp;
        sm1w[mpp * 512 + k] = make_float2(W_fh[(size_t)mg0 * 512 + k],
                                          W_fh[(size_t)(mg0 + 1) * 512 + k]);
    }
    __syncthreads();

    const int m_own = tid >> 5;
    const int b0    = 2 * (tid & 31);
    const int m_g   = blk * 4 + m_own;
    const int mp_o  = m_own >> 1;
    const int ml_o  = m_own & 1;
    int bq_o, pr_o;
    if (b0 < 32) { bq_o = b0 >> 2; pr_o = (b0 >> 1) & 1; }
    else         { int bb = b0 - 32; bq_o = bb >> 2; pr_o = 2 + ((bb >> 1) & 1); }

    float bfv = 0.f, biv = 0.f, bov = 0.f, bocv = 0.f, bfhv = 0.f;
    float2 c_reg = make_float2(0.f, 0.f);
    float2 af2, ai2, ao2, aoc2, act2, aw2;
    if (tid < 128) {
        bfv  = b_iouh[m_g];
        biv  = b_iouh[512 + m_g];
        bov  = b_iouh[1024 + m_g];
        bocv = b_iouh[1536 + m_g];
        bfhv = b_fh[m_g];
        c_reg.x = c0[(size_t)b0 * 512 + m_g];
        c_reg.y = c0[(size_t)(b0 + 1) * 512 + m_g];
        const size_t ib = ((size_t)0 * 4 * 512 + m_g) * 64 + b0;
        const size_t sb = (size_t)m_g * 64 + b0;
        af2  = *reinterpret_cast<const float2*>(&g_iouT[ib]);
        ai2  = *reinterpret_cast<const float2*>(&g_iouT[ib + 1 * 512 * 64]);
        ao2  = *reinterpret_cast<const float2*>(&g_iouT[ib + 2 * 512 * 64]);
        aoc2 = *reinterpret_cast<const float2*>(&g_iouT[ib + 3 * 512 * 64]);
        act2 = *reinterpret_cast<const float2*>(&g_ctxT[sb]);
        aw2  = *reinterpret_cast<const float2*>(&g_wcsT[sb]);
    }

    const int kbase = kc * 128 + iq * 32;
    const int fbase = kbase * 16 + bq;
    float2 h_keep = make_float2(0.f, 0.f);

    for (int t = 0; t < SEQ_T; t++) {
        const float* hb = (t == 0) ? g_h0T : (g_hT + (size_t)(t - 1) * (DIM * NB));
        const float4* hp = reinterpret_cast<const float4*>(hb);

        ull A[2][5][4];
        #pragma unroll
        for (int a1 = 0; a1 < 2; a1++)
            #pragma unroll
            for (int a2 = 0; a2 < 5; a2++)
                #pragma unroll
                for (int a3 = 0; a3 < 4; a3++) A[a1][a2][a3] = 0ull;

        #pragma unroll 4
        for (int i = 0; i < 32; i++) {
            float4 hl = __ldg(hp + fbase + i * 16);
            float4 hh = __ldg(hp + fbase + 8 + i * 16);
            ull hpair[4];
            hpair[0] = reinterpret_cast<ulonglong2*>(&hl)->x;
            hpair[1] = reinterpret_cast<ulonglong2*>(&hl)->y;
            hpair[2] = reinterpret_cast<ulonglong2*>(&hh)->x;
            hpair[3] = reinterpret_cast<ulonglong2*>(&hh)->y;

            float wa[10];
            *reinterpret_cast<float4*>(wa + 0) = sm4w[(mp * 2 + 0) * 512 + kbase + i];
            *reinterpret_cast<float4*>(wa + 4) = sm4w[(mp * 2 + 1) * 512 + kbase + i];
            *reinterpret_cast<float2*>(wa + 8) = sm1w[mp * 512 + kbase + i];

            #pragma unroll
            for (int ml = 0; ml < 2; ml++) {
                #pragma unroll
                for (int g = 0; g < 5; g++) {
                    float w = (g < 4) ? wa[ml * 4 + g] : wa[8 + ml];
                    ull wd = packdup(w);
                    #pragma unroll
                    for (int pr = 0; pr < 4; pr++)
                        ffma2(A[ml][g][pr], hpair[pr], wd);
                }
            }
        }

        ull* Af = &A[0][0][0];
        #pragma unroll
        for (int c = 0; c < 40; c++) {
            float2 v = *reinterpret_cast<float2*>(&Af[c]);
            v.x += __shfl_xor_sync(0xffffffffu, v.x, 8);
            v.y += __shfl_xor_sync(0xffffffffu, v.y, 8);
            v.x += __shfl_xor_sync(0xffffffffu, v.x, 16);
            v.y += __shfl_xor_sync(0xffffffffu, v.y, 16);
            Af[c] = *reinterpret_cast<ull*>(&v);
        }

        #pragma unroll
        for (int cc = 0; cc < 10; cc++) {
            int c = kc * 10 + cc;
            buf[((size_t)warp * 40 + c) * 8 + bq] = Af[c];
        }
        __syncthreads();

        if (tid < 128) {
            float2 s[5];
            #pragma unroll
            for (int g = 0; g < 5; g++) {
                int c = ml_o * 20 + g * 4 + pr_o;
                float2 acc2 = make_float2(0.f, 0.f);
                #pragma unroll
                for (int q = 0; q < 4; q++) {
                    ull v = buf[((size_t)(mp_o * 4 + q) * 40 + c) * 8 + bq_o];
                    float2 f = *reinterpret_cast<float2*>(&v);
                    acc2.x += f.x; acc2.y += f.y;
                }
                s[g] = acc2;
            }

            float fgx  = sigmoid_fast(s[0].x + af2.x + bfv);
            float fgy  = sigmoid_fast(s[0].y + af2.y + bfv);
            float igx  = sigmoid_fast(s[1].x + ai2.x + biv);
            float igy  = sigmoid_fast(s[1].y + ai2.y + biv);
            float ogx  = sigmoid_fast(s[2].x + ao2.x + bov);
            float ogy  = sigmoid_fast(s[2].y + ao2.y + bov);
            float ocgx = sigmoid_fast(s[3].x + aoc2.x + bocv);
            float ocgy = sigmoid_fast(s[3].y + aoc2.y + bocv);
            float ctx_ = tanh_fast(s[4].x + act2.x + bfhv);
            float cty_ = tanh_fast(s[4].y + act2.y + bfhv);

            c_reg.x = igx * ctx_ + fgx * c_reg.x;
            c_reg.y = igy * cty_ + fgy * c_reg.y;
            h_keep.x = ogx * tanh_fast(c_reg.x) + ocgx * aw2.x;
            h_keep.y = ogy * tanh_fast(c_reg.y) + ocgy * aw2.y;

            *reinterpret_cast<float2*>(&g_hT[(size_t)t * (DIM * NB) + (size_t)m_g * 64 + b0]) = h_keep;
            out[(size_t)t * (NB * DIM) + (size_t)b0 * 512 + m_g]       = h_keep.x;
            out[(size_t)t * (NB * DIM) + (size_t)(b0 + 1) * 512 + m_g] = h_keep.y;

            if (t + 1 < SEQ_T) {
                const size_t ib2 = (((size_t)(t + 1) * 4) * 512 + m_g) * 64 + b0;
                const size_t sb2 = (size_t)(t + 1) * (512 * 64) + (size_t)m_g * 64 + b0;
                af2  = *reinterpret_cast<const float2*>(&g_iouT[ib2]);
                ai2  = *reinterpret_cast<const float2*>(&g_iouT[ib2 + 1 * 512 * 64]);
                ao2  = *reinterpret_cast<const float2*>(&g_iouT[ib2 + 2 * 512 * 64]);
                aoc2 = *reinterpret_cast<const float2*>(&g_iouT[ib2 + 3 * 512 * 64]);
                act2 = *reinterpret_cast<const float2*>(&g_ctxT[sb2]);
                aw2  = *reinterpret_cast<const float2*>(&g_wcsT[sb2]);
            }
        }

        __syncthreads();
        if (tid == 0) {
            __threadfence();
            atomicAdd(&g_cnt, 1u);
            const unsigned target = (unsigned)gridDim.x * (unsigned)(t + 1);
            while (*reinterpret_cast<volatile unsigned*>(&g_cnt) < target) { }
            __threadfence();
        }
        __syncthreads();
    }

    if (tid < 128) {
        out[TBM + (size_t)b0 * 512 + m_g]                  = c_reg.x;
        out[TBM + (size_t)(b0 + 1) * 512 + m_g]            = c_reg.y;
        out[TBM + NB * DIM + (size_t)b0 * 512 + m_g]       = h_keep.x;
        out[TBM + NB * DIM + (size_t)(b0 + 1) * 512 + m_g] = h_keep.y;
    }
}

// ---------------------------------------------------------------------------
extern "C" void kernel_launch(void* const* d_in, const int* in_sizes, int n_in,
                              void* d_out, int out_size)
{
    const float* inputs = (const float*)d_in[0];
    const float* emb_s  = (const float*)d_in[1];
    const float* c0     = (const float*)d_in[2];
    const float* h0     = (const float*)d_in[3];
    const float* W_ioux = (const float*)d_in[4];
    const float* b_ioux = (const float*)d_in[5];
    const float* W_iouh = (const float*)d_in[6];
    const float* b_iouh = (const float*)d_in[7];
    const float* W_ious = (const float*)d_in[8];
    const float* b_ious = (const float*)d_in[9];
    const float* W_fx   = (const float*)d_in[10];
    const float* b_fx   = (const float*)d_in[11];
    const float* W_fh   = (const float*)d_in[12];
    const float* b_fh   = (const float*)d_in[13];
    const float* W_wc   = (const float*)d_in[14];
    const float* b_wc   = (const float*)d_in[15];
    float* out = (float*)d_out;

    static int smem_set = 0;
    if (!smem_set) {
        cudaFuncSetAttribute(scan_kernel, cudaFuncAttributeMaxDynamicSharedMemorySize,
                             SCAN_SMEM_BYTES);
        cudaFuncSetAttribute(gemm_tc_kernel, cudaFuncAttributeMaxDynamicSharedMemorySize,
                             G_SMEM_TOTAL);
        smem_set = 1;
    }

    init_kernel<<<64, 512>>>(h0);
    gemm_tc_kernel<<<3072, 512, G_SMEM_TOTAL>>>(inputs, emb_s, W_ioux, W_ious,
                                                b_ioux, b_ious, W_fx, b_fx, W_wc, b_wc);
    scan_kernel<<<128, 256, SCAN_SMEM_BYTES>>>(W_iouh, b_iouh, W_fh, b_fh, c0, out);
}

// round 10
// speedup vs baseline: 1.9054x; 1.0881x over previous
#include <cuda_runtime.h>
#include <cuda_bf16.h>
#include <math.h>
#include <stdint.h>

#define SEQ_T 256
#define NB    64
#define DIM   512
#define TBM   (SEQ_T * NB * DIM)   /* 8388608 */

// ---------------- scratch (static device memory; no runtime alloc) ----------
__device__ float g_iouT[(size_t)SEQ_T * 4 * DIM * NB];  // [t][gate][m][b]
__device__ float g_ctxT[(size_t)SEQ_T * DIM * NB];      // [t][m][b]
__device__ float g_wcsT[(size_t)SEQ_T * DIM * NB];      // [t][m][b]  (tanh applied)
__device__ float g_hT  [(size_t)SEQ_T * DIM * NB];      // [t][m][b]  h history
__device__ float g_h0T [DIM * NB];                      // [m][b]
__device__ unsigned g_cnt;                              // grid-barrier counter

// pre-converted bf16 hi/lo operands
__device__ __align__(16) unsigned short g_Ahi[(size_t)16384 * 1024];
__device__ __align__(16) unsigned short g_Alo[(size_t)16384 * 1024];
__device__ __align__(16) unsigned short g_Wih[(size_t)2048 * 1024];
__device__ __align__(16) unsigned short g_Wil[(size_t)2048 * 1024];
__device__ __align__(16) unsigned short g_Wfh2[512 * 512];
__device__ __align__(16) unsigned short g_Wfl2[512 * 512];
__device__ __align__(16) unsigned short g_Wch2[512 * 512];
__device__ __align__(16) unsigned short g_Wcl2[512 * 512];

typedef unsigned long long ull;

__device__ __forceinline__ void ffma2(ull& d, ull a, ull b) {
    asm("fma.rn.f32x2 %0, %1, %2, %0;" : "+l"(d) : "l"(a), "l"(b));
}
__device__ __forceinline__ ull packdup(float a) {
    ull r; asm("mov.b64 %0, {%1, %1};" : "=l"(r) : "f"(a)); return r;
}
__device__ __forceinline__ float tanh_fast(float x) {
    float y; asm("tanh.approx.f32 %0, %1;" : "=f"(y) : "f"(x)); return y;
}
__device__ __forceinline__ float sigmoid_fast(float x) {
    return fmaf(0.5f, tanh_fast(0.5f * x), 0.5f);
}
__device__ __forceinline__ uint32_t smem_u32(const void* p) {
    uint32_t a;
    asm("{ .reg .u64 t; cvta.to.shared.u64 t, %1; cvt.u32.u64 %0, t; }" : "=r"(a) : "l"(p));
    return a;
}
__device__ __forceinline__ void ldsm4(uint32_t* r, uint32_t addr) {
    asm volatile("ldmatrix.sync.aligned.m8n8.x4.shared.b16 {%0,%1,%2,%3}, [%4];"
                 : "=r"(r[0]), "=r"(r[1]), "=r"(r[2]), "=r"(r[3]) : "r"(addr));
}
__device__ __forceinline__ void mma_bf16(float* d, const uint32_t* a, const uint32_t* b) {
    asm volatile(
        "mma.sync.aligned.m16n8k16.row.col.f32.bf16.bf16.f32 "
        "{%0,%1,%2,%3}, {%4,%5,%6,%7}, {%8,%9}, {%0,%1,%2,%3};"
        : "+f"(d[0]), "+f"(d[1]), "+f"(d[2]), "+f"(d[3])
        : "r"(a[0]), "r"(a[1]), "r"(a[2]), "r"(a[3]), "r"(b[0]), "r"(b[1]));
}
__device__ __forceinline__ void cp16(uint32_t dst, const void* src) {
    asm volatile("cp.async.ca.shared.global [%0], [%1], 16;" :: "r"(dst), "l"(src));
}

// ---------------------------------------------------------------------------
__global__ void init_kernel(const float* __restrict__ h0) {
    int b = blockIdx.x;          // 64 blocks
    int m = threadIdx.x;         // 512 threads
    g_h0T[m * NB + b] = h0[b * DIM + m];
    if (b == 0 && m == 0) g_cnt = 0u;
}

// ---------------------------------------------------------------------------
// fp32 -> bf16 hi/lo pre-conversion. src rows of 512 contiguous floats;
// dst [row][col_off + k] with element pitch dst_pitch. 4 elements/thread.
// ---------------------------------------------------------------------------
__global__ void __launch_bounds__(256) conv_kernel(
    const float4* __restrict__ src, unsigned short* __restrict__ hi,
    unsigned short* __restrict__ lo, int dst_pitch, int col_off, int nthreads)
{
    int idx = blockIdx.x * 256 + threadIdx.x;
    if (idx >= nthreads) return;
    int r  = idx >> 7;
    int c4 = (idx & 127) << 2;
    float4 v = __ldg(src + idx);
    __nv_bfloat16 h0 = __float2bfloat16_rn(v.x);
    __nv_bfloat16 h1 = __float2bfloat16_rn(v.y);
    __nv_bfloat16 h2 = __float2bfloat16_rn(v.z);
    __nv_bfloat16 h3 = __float2bfloat16_rn(v.w);
    __nv_bfloat16 l0 = __float2bfloat16_rn(v.x - __bfloat162float(h0));
    __nv_bfloat16 l1 = __float2bfloat16_rn(v.y - __bfloat162float(h1));
    __nv_bfloat16 l2 = __float2bfloat16_rn(v.z - __bfloat162float(h2));
    __nv_bfloat16 l3 = __float2bfloat16_rn(v.w - __bfloat162float(h3));
    uint2 hp, lp;
    hp.x = ((unsigned)__bfloat16_as_ushort(h1) << 16) | __bfloat16_as_ushort(h0);
    hp.y = ((unsigned)__bfloat16_as_ushort(h3) << 16) | __bfloat16_as_ushort(h2);
    lp.x = ((unsigned)__bfloat16_as_ushort(l1) << 16) | __bfloat16_as_ushort(l0);
    lp.y = ((unsigned)__bfloat16_as_ushort(l3) << 16) | __bfloat16_as_ushort(l2);
    size_t d = (size_t)r * dst_pitch + col_off + c4;
    *reinterpret_cast<uint2*>(hi + d) = hp;
    *reinterpret_cast<uint2*>(lo + d) = lp;
}

// ---------------------------------------------------------------------------
// HMMA fused GEMM on pre-converted bf16 (split hi+lo, fp32 accum), cp.async
// double-buffered staging. 512 threads, 16 warps, warp tile 32x32.
//   blocks [0,2048)    : iou_x  (N=2048, K=1024)
//   blocks [2048,2560) : ctx    (N=512,  K=512)
//   blocks [2560,3072) : wcs    (N=512,  K=512, tanh epilogue)
// ---------------------------------------------------------------------------
#define GB_BUF   40960                /* one buffer: 4 tiles * 128*40*2B */
#define GB_A_HI  0
#define GB_A_LO  10240
#define GB_B_HI  20480
#define GB_B_LO  30720
#define G_SMEM_TOTAL (2 * GB_BUF)     /* 81920; epilogue (128*136*4=69632) reuses it */

__global__ void __launch_bounds__(512) gemm_tc_kernel(
    const float* __restrict__ b_ioux, const float* __restrict__ b_ious,
    const float* __restrict__ b_fx,   const float* __restrict__ b_wc)
{
    extern __shared__ char smem[];
    __shared__ float bias_sm[128];
    const uint32_t sbase = smem_u32(smem);

    const int tid  = threadIdx.x;
    const int wid  = tid >> 5;
    const int lane = tid & 31;
    const int blk  = blockIdx.x;

    int mode, bx, by, K, acol0, bpitch;
    const unsigned short *Bh, *Bl;
    if (blk < 2048) {
        mode = 0; bx = blk & 15; by = blk >> 4; K = 1024; acol0 = 0;
        Bh = g_Wih; Bl = g_Wil; bpitch = 1024;
    } else if (blk < 2560) {
        int l = blk - 2048;
        mode = 1; bx = l & 3; by = l >> 2; K = 512; acol0 = 0;
        Bh = g_Wfh2; Bl = g_Wfl2; bpitch = 512;
    } else {
        int l = blk - 2560;
        mode = 2; bx = l & 3; by = l >> 2; K = 512; acol0 = 512;
        Bh = g_Wch2; Bl = g_Wcl2; bpitch = 512;
    }
    const int bm = by * 128;
    const int bn = bx * 128;
    const int t0 = bm >> 6;

    if (tid < 128) {
        float v;
        if (mode == 0)      v = b_ioux[bn + tid] + b_ious[bn + tid];
        else if (mode == 1) v = b_fx[bn + tid];
        else                v = b_wc[bn + tid];
        bias_sm[tid] = v;
    }

    const int m0 = (wid & 3) * 32;
    const int n0 = (wid >> 2) * 32;

    float acc[2][4][4];
    #pragma unroll
    for (int i = 0; i < 2; i++)
        #pragma unroll
        for (int j = 0; j < 4; j++)
            #pragma unroll
            for (int e = 0; e < 4; e++) acc[i][j][e] = 0.f;

    const uint32_t aoff = (uint32_t)((lane & 15) * 80 + (lane >> 4) * 16);
    const uint32_t boff = (uint32_t)((((lane >> 4) << 3) + (lane & 7)) * 80 + ((lane >> 3) & 1) * 16);

    const int sr = tid >> 2;          // staging row 0..127
    const int sq = tid & 3;           // 16B chunk within 64B row

    const int nc = K >> 5;

    // stage chunk 0
    {
        int kg = 0;
        uint32_t d = sbase + (uint32_t)(sr * 80 + sq * 16);
        const unsigned short* as = g_Ahi + (size_t)(bm + sr) * 1024 + acol0 + kg;
        const unsigned short* al = g_Alo + (size_t)(bm + sr) * 1024 + acol0 + kg;
        const unsigned short* bh = Bh + (size_t)(bn + sr) * bpitch + kg;
        const unsigned short* bl = Bl + (size_t)(bn + sr) * bpitch + kg;
        cp16(d + GB_A_HI, (const char*)as + sq * 16);
        cp16(d + GB_A_LO, (const char*)al + sq * 16);
        cp16(d + GB_B_HI, (const char*)bh + sq * 16);
        cp16(d + GB_B_LO, (const char*)bl + sq * 16);
        asm volatile("cp.async.commit_group;");
    }

    for (int c = 0; c < nc; c++) {
        const int p = c & 1;
        const uint32_t bufb = sbase + p * GB_BUF;

        if (c + 1 < nc) {
            int kg = (c + 1) * 32;
            uint32_t d = sbase + (p ^ 1) * GB_BUF + (uint32_t)(sr * 80 + sq * 16);
            const unsigned short* as = g_Ahi + (size_t)(bm + sr) * 1024 + acol0 + kg;
            const unsigned short* al = g_Alo + (size_t)(bm + sr) * 1024 + acol0 + kg;
            const unsigned short* bh = Bh + (size_t)(bn + sr) * bpitch + kg;
            const unsigned short* bl = Bl + (size_t)(bn + sr) * bpitch + kg;
            cp16(d + GB_A_HI, (const char*)as + sq * 16);
            cp16(d + GB_A_LO, (const char*)al + sq * 16);
            cp16(d + GB_B_HI, (const char*)bh + sq * 16);
            cp16(d + GB_B_LO, (const char*)bl + sq * 16);
            asm volatile("cp.async.commit_group;");
            asm volatile("cp.async.wait_group 1;");
        } else {
            asm volatile("cp.async.wait_group 0;");
        }
        __syncthreads();

        #pragma unroll
        for (int s = 0; s < 2; s++) {
            const uint32_t kkb = s * 32;
            uint32_t a_h[2][4], a_l[2][4], b_h[2][4], b_l[2][4];
            #pragma unroll
            for (int mt = 0; mt < 2; mt++) {
                uint32_t ad = bufb + (uint32_t)((m0 + mt * 16) * 80) + aoff + kkb;
                ldsm4(a_h[mt], ad + GB_A_HI);
                ldsm4(a_l[mt], ad + GB_A_LO);
            }
            #pragma unroll
            for (int pq = 0; pq < 2; pq++) {
                uint32_t bd = bufb + (uint32_t)((n0 + pq * 16) * 80) + boff + kkb;
                ldsm4(b_h[pq], bd + GB_B_HI);
                ldsm4(b_l[pq], bd + GB_B_LO);
            }
            #pragma unroll
            for (int mt = 0; mt < 2; mt++) {
                #pragma unroll
                for (int nt = 0; nt < 4; nt++) {
                    const uint32_t* bh = &b_h[nt >> 1][(nt & 1) * 2];
                    const uint32_t* bl = &b_l[nt >> 1][(nt & 1) * 2];
                    mma_bf16(acc[mt][nt], a_h[mt], bh);
                    mma_bf16(acc[mt][nt], a_h[mt], bl);
                    mma_bf16(acc[mt][nt], a_l[mt], bh);
                }
            }
        }
        __syncthreads();
    }

    // ---- epilogue: acc -> smem transpose (stride 136) -> coalesced stores ----
    float* ep = reinterpret_cast<float*>(smem);
    #pragma unroll
    for (int mt = 0; mt < 2; mt++)
        #pragma unroll
        for (int nt = 0; nt < 4; nt++)
            #pragma unroll
            for (int e = 0; e < 4; e++) {
                int m = m0 + mt * 16 + (lane >> 2) + (e >> 1) * 8;
                int n = n0 + nt * 8 + (lane & 3) * 2 + (e & 1);
                float v = acc[mt][nt][e] + bias_sm[n];
                if (mode == 2) v = tanhf(v);
                ep[n * 136 + m] = v;
            }
    __syncthreads();

    #pragma unroll
    for (int i = 0; i < 8; i++) {
        int q   = tid + i * 512;
        int col = q >> 5;
        int f4  = q & 31;
        int m   = f4 * 4;
        float4 val = *reinterpret_cast<float4*>(ep + col * 136 + m);
        int cn = bn + col;
        int t  = t0 + (m >> 6);
        int b  = m & 63;
        float* dst;
        if (mode == 0)
            dst = g_iouT + (((size_t)t * 4 + (cn >> 9)) * 512 + (cn & 511)) * 64 + b;
        else if (mode == 1)
            dst = g_ctxT + ((size_t)t * 512 + cn) * 64 + b;
        else
            dst = g_wcsT + ((size_t)t * 512 + cn) * 64 + b;
        *reinterpret_cast<float4*>(dst) = val;
    }
}

// ---------------------------------------------------------------------------
// Persistent scan (R7 structure + kc-skewed weight smem: conflict-free LDS).
// ---------------------------------------------------------------------------
#define SM4_FLOATS 8256               /* 4 ml * 516 float4 */
#define SM1_FLOATS 2080               /* 2 mp * 520 float2 */
#define SM4_BYTES  (SM4_FLOATS * 4)   /* 33024 */
#define SM1_BYTES  (SM1_FLOATS * 4)   /* 8320  */
#define BUF_BYTES  20480
#define SCAN_SMEM_BYTES (SM4_BYTES + SM1_BYTES + BUF_BYTES)   /* 61824 */

__global__ void __launch_bounds__(256) scan_kernel(
    const float* __restrict__ W_iouh, const float* __restrict__ b_iouh,
    const float* __restrict__ W_fh,   const float* __restrict__ b_fh,
    const float* __restrict__ c0,     float* __restrict__ out)
{
    extern __shared__ char smraw[];
    float4* sm4w = reinterpret_cast<float4*>(smraw);
    float2* sm1w = reinterpret_cast<float2*>(smraw + SM4_BYTES);
    ull*    buf  = reinterpret_cast<ull*>(smraw + SM4_BYTES + SM1_BYTES);

    const int tid  = threadIdx.x;
    const int warp = tid >> 5;
    const int lane = tid & 31;
    const int mp   = warp >> 2;
    const int iq   = warp & 3;
    const int kc   = lane >> 3;
    const int bq   = lane & 7;
    const int blk  = blockIdx.x;

    // gate weights: [ml][kc(129 skew)][i]
    for (int idx = tid; idx < 2048; idx += 256) {
        int ml = idx >> 9;
        int k  = idx & 511;
        int mg = blk * 4 + ml;
        sm4w[ml * 516 + (k >> 7) * 129 + (k & 127)] = make_float4(
            W_iouh[(size_t)mg * 512 + k],
            W_iouh[(size_t)(512 + mg) * 512 + k],
            W_iouh[(size_t)(1024 + mg) * 512 + k],
            W_iouh[(size_t)(1536 + mg) * 512 + k]);
    }
    // W_fh pairs: [mp][kc(130 skew)][i]
    for (int idx = tid; idx < 1024; idx += 256) {
        int mpp = idx >> 9;
        int k   = idx & 511;
        int mg0 = blk * 4 + 2 * mpp;
        sm1w[mpp * 520 + (k >> 7) * 130 + (k & 127)] =
            make_float2(W_fh[(size_t)mg0 * 512 + k], W_fh[(size_t)(mg0 + 1) * 512 + k]);
    }
    __syncthreads();

    const int m_own = tid >> 5;
    const int b0    = 2 * (tid & 31);
    const int m_g   = blk * 4 + m_own;
    const int mp_o  = m_own >> 1;
    const int ml_o  = m_own & 1;
    int bq_o, pr_o;
    if (b0 < 32) { bq_o = b0 >> 2; pr_o = (b0 >> 1) & 1; }
    else         { int bb = b0 - 32; bq_o = bb >> 2; pr_o = 2 + ((bb >> 1) & 1); }

    float bfv = 0.f, biv = 0.f, bov = 0.f, bocv = 0.f, bfhv = 0.f;
    float2 c_reg = make_float2(0.f, 0.f);
    float2 af2, ai2, ao2, aoc2, act2, aw2;
    if (tid < 128) {
        bfv  = b_iouh[m_g];
        biv  = b_iouh[512 + m_g];
        bov  = b_iouh[1024 + m_g];
        bocv = b_iouh[1536 + m_g];
        bfhv = b_fh[m_g];
        c_reg.x = c0[(size_t)b0 * 512 + m_g];
        c_reg.y = c0[(size_t)(b0 + 1) * 512 + m_g];
        const size_t ib = ((size_t)0 * 4 * 512 + m_g) * 64 + b0;
        const size_t sb = (size_t)m_g * 64 + b0;
        af2  = *reinterpret_cast<const float2*>(&g_iouT[ib]);
        ai2  = *reinterpret_cast<const float2*>(&g_iouT[ib + 1 * 512 * 64]);
        ao2  = *reinterpret_cast<const float2*>(&g_iouT[ib + 2 * 512 * 64]);
        aoc2 = *reinterpret_cast<const float2*>(&g_iouT[ib + 3 * 512 * 64]);
        act2 = *reinterpret_cast<const float2*>(&g_ctxT[sb]);
        aw2  = *reinterpret_cast<const float2*>(&g_wcsT[sb]);
    }

    const int kbase = kc * 128 + iq * 32;               // h indexing (unskewed)
    const int fbase = kbase * 16 + bq;
    const int w4base = kc * 129 + iq * 32;              // skewed weight indexing
    const int w1base = kc * 130 + iq * 32;
    float2 h_keep = make_float2(0.f, 0.f);

    for (int t = 0; t < SEQ_T; t++) {
        const float* hb = (t == 0) ? g_h0T : (g_hT + (size_t)(t - 1) * (DIM * NB));
        const float4* hp = reinterpret_cast<const float4*>(hb);

        ull A[2][5][4];
        #pragma unroll
        for (int a1 = 0; a1 < 2; a1++)
            #pragma unroll
            for (int a2 = 0; a2 < 5; a2++)
                #pragma unroll
                for (int a3 = 0; a3 < 4; a3++) A[a1][a2][a3] = 0ull;

        #pragma unroll 4
        for (int i = 0; i < 32; i++) {
            float4 hl = __ldg(hp + fbase + i * 16);
            float4 hh = __ldg(hp + fbase + 8 + i * 16);
            ull hpair[4];
            hpair[0] = reinterpret_cast<ulonglong2*>(&hl)->x;
            hpair[1] = reinterpret_cast<ulonglong2*>(&hl)->y;
            hpair[2] = reinterpret_cast<ulonglong2*>(&hh)->x;
            hpair[3] = reinterpret_cast<ulonglong2*>(&hh)->y;

            float wa[10];
            *reinterpret_cast<float4*>(wa + 0) = sm4w[(mp * 2 + 0) * 516 + w4base + i];
            *reinterpret_cast<float4*>(wa + 4) = sm4w[(mp * 2 + 1) * 516 + w4base + i];
            *reinterpret_cast<float2*>(wa + 8) = sm1w[mp * 520 + w1base + i];

            #pragma unroll
            for (int ml = 0; ml < 2; ml++) {
                #pragma unroll
                for (int g = 0; g < 5; g++) {
                    float w = (g < 4) ? wa[ml * 4 + g] : wa[8 + ml];
                    ull wd = packdup(w);
                    #pragma unroll
                    for (int pr = 0; pr < 4; pr++)
                        ffma2(A[ml][g][pr], hpair[pr], wd);
                }
            }
        }

        ull* Af = &A[0][0][0];
        #pragma unroll
        for (int c = 0; c < 40; c++) {
            float2 v = *reinterpret_cast<float2*>(&Af[c]);
            v.x += __shfl_xor_sync(0xffffffffu, v.x, 8);
            v.y += __shfl_xor_sync(0xffffffffu, v.y, 8);
            v.x += __shfl_xor_sync(0xffffffffu, v.x, 16);
            v.y += __shfl_xor_sync(0xffffffffu, v.y, 16);
            Af[c] = *reinterpret_cast<ull*>(&v);
        }

        #pragma unroll
        for (int cc = 0; cc < 10; cc++) {
            int c = kc * 10 + cc;
            buf[((size_t)warp * 40 + c) * 8 + bq] = Af[c];
        }
        __syncthreads();

        if (tid < 128) {
            float2 s[5];
            #pragma unroll
            for (int g = 0; g < 5; g++) {
                int c = ml_o * 20 + g * 4 + pr_o;
                float2 acc2 = make_float2(0.f, 0.f);
                #pragma unroll
                for (int q = 0; q < 4; q++) {
                    ull v = buf[((size_t)(mp_o * 4 + q) * 40 + c) * 8 + bq_o];
                    float2 f = *reinterpret_cast<float2*>(&v);
                    acc2.x += f.x; acc2.y += f.y;
                }
                s[g] = acc2;
            }

            float fgx  = sigmoid_fast(s[0].x + af2.x + bfv);
            float fgy  = sigmoid_fast(s[0].y + af2.y + bfv);
            float igx  = sigmoid_fast(s[1].x + ai2.x + biv);
            float igy  = sigmoid_fast(s[1].y + ai2.y + biv);
            float ogx  = sigmoid_fast(s[2].x + ao2.x + bov);
            float ogy  = sigmoid_fast(s[2].y + ao2.y + bov);
            float ocgx = sigmoid_fast(s[3].x + aoc2.x + bocv);
            float ocgy = sigmoid_fast(s[3].y + aoc2.y + bocv);
            float ctx_ = tanh_fast(s[4].x + act2.x + bfhv);
            float cty_ = tanh_fast(s[4].y + act2.y + bfhv);

            c_reg.x = igx * ctx_ + fgx * c_reg.x;
            c_reg.y = igy * cty_ + fgy * c_reg.y;
            h_keep.x = ogx * tanh_fast(c_reg.x) + ocgx * aw2.x;
            h_keep.y = ogy * tanh_fast(c_reg.y) + ocgy * aw2.y;

            *reinterpret_cast<float2*>(&g_hT[(size_t)t * (DIM * NB) + (size_t)m_g * 64 + b0]) = h_keep;
            out[(size_t)t * (NB * DIM) + (size_t)b0 * 512 + m_g]       = h_keep.x;
            out[(size_t)t * (NB * DIM) + (size_t)(b0 + 1) * 512 + m_g] = h_keep.y;

            if (t + 1 < SEQ_T) {
                const size_t ib2 = (((size_t)(t + 1) * 4) * 512 + m_g) * 64 + b0;
                const size_t sb2 = (size_t)(t + 1) * (512 * 64) + (size_t)m_g * 64 + b0;
                af2  = *reinterpret_cast<const float2*>(&g_iouT[ib2]);
                ai2  = *reinterpret_cast<const float2*>(&g_iouT[ib2 + 1 * 512 * 64]);
                ao2  = *reinterpret_cast<const float2*>(&g_iouT[ib2 + 2 * 512 * 64]);
                aoc2 = *reinterpret_cast<const float2*>(&g_iouT[ib2 + 3 * 512 * 64]);
                act2 = *reinterpret_cast<const float2*>(&g_ctxT[sb2]);
                aw2  = *reinterpret_cast<const float2*>(&g_wcsT[sb2]);
            }
        }

        __syncthreads();
        if (tid == 0) {
            __threadfence();
            atomicAdd(&g_cnt, 1u);
            const unsigned target = (unsigned)gridDim.x * (unsigned)(t + 1);
            while (*reinterpret_cast<volatile unsigned*>(&g_cnt) < target) { }
            __threadfence();
        }
        __syncthreads();
    }

    if (tid < 128) {
        out[TBM + (size_t)b0 * 512 + m_g]                  = c_reg.x;
        out[TBM + (size_t)(b0 + 1) * 512 + m_g]            = c_reg.y;
        out[TBM + NB * DIM + (size_t)b0 * 512 + m_g]       = h_keep.x;
        out[TBM + NB * DIM + (size_t)(b0 + 1) * 512 + m_g] = h_keep.y;
    }
}

// ---------------------------------------------------------------------------
extern "C" void kernel_launch(void* const* d_in, const int* in_sizes, int n_in,
                              void* d_out, int out_size)
{
    const float* inputs = (const float*)d_in[0];
    const float* emb_s  = (const float*)d_in[1];
    const float* c0     = (const float*)d_in[2];
    const float* h0     = (const float*)d_in[3];
    const float* W_ioux = (const float*)d_in[4];
    const float* b_ioux = (const float*)d_in[5];
    const float* W_iouh = (const float*)d_in[6];
    const float* b_iouh = (const float*)d_in[7];
    const float* W_ious = (const float*)d_in[8];
    const float* b_ious = (const float*)d_in[9];
    const float* W_fx   = (const float*)d_in[10];
    const float* b_fx   = (const float*)d_in[11];
    const float* W_fh   = (const float*)d_in[12];
    const float* b_fh   = (const float*)d_in[13];
    const float* W_wc   = (const float*)d_in[14];
    const float* b_wc   = (const float*)d_in[15];
    float* out = (float*)d_out;

    static int smem_set = 0;
    if (!smem_set) {
        cudaFuncSetAttribute(scan_kernel, cudaFuncAttributeMaxDynamicSharedMemorySize,
                             SCAN_SMEM_BYTES);
        cudaFuncSetAttribute(gemm_tc_kernel, cudaFuncAttributeMaxDynamicSharedMemorySize,
                             G_SMEM_TOTAL);
        smem_set = 1;
    }

    unsigned short *Ahi, *Alo, *Wih, *Wil, *Wfh2, *Wfl2, *Wch2, *Wcl2;
    cudaGetSymbolAddress((void**)&Ahi,  g_Ahi);
    cudaGetSymbolAddress((void**)&Alo,  g_Alo);
    cudaGetSymbolAddress((void**)&Wih,  g_Wih);
    cudaGetSymbolAddress((void**)&Wil,  g_Wil);
    cudaGetSymbolAddress((void**)&Wfh2, g_Wfh2);
    cudaGetSymbolAddress((void**)&Wfl2, g_Wfl2);
    cudaGetSymbolAddress((void**)&Wch2, g_Wch2);
    cudaGetSymbolAddress((void**)&Wcl2, g_Wcl2);

    init_kernel<<<64, 512>>>(h0);
    // pre-convert operands to bf16 hi/lo
    conv_kernel<<<8192, 256>>>((const float4*)inputs, Ahi, Alo, 1024, 0,   16384 * 128);
    conv_kernel<<<8192, 256>>>((const float4*)emb_s,  Ahi, Alo, 1024, 512, 16384 * 128);
    conv_kernel<<<1024, 256>>>((const float4*)W_ioux, Wih, Wil, 1024, 0,   2048 * 128);
    conv_kernel<<<1024, 256>>>((const float4*)W_ious, Wih, Wil, 1024, 512, 2048 * 128);
    conv_kernel<<<256, 256>>>((const float4*)W_fx,    Wfh2, Wfl2, 512, 0,  512 * 128);
    conv_kernel<<<256, 256>>>((const float4*)W_wc,    Wch2, Wcl2, 512, 0,  512 * 128);

    gemm_tc_kernel<<<3072, 512, G_SMEM_TOTAL>>>(b_ioux, b_ious, b_fx, b_wc);
    scan_kernel<<<128, 256, SCAN_SMEM_BYTES>>>(W_iouh, b_iouh, W_fh, b_fh, c0, out);
}